// round 16
// baseline (speedup 1.0000x reference)
#include <cuda_runtime.h>
#include <cuda_fp16.h>
#include <cstdint>

#define NSEQ 512
#define DMODEL 128
#define LN_EPS 1e-5f
#define TILE_U32 8704          // 128 * 68

// ---- scratch (device globals; no runtime allocation) ----
__device__ uint32_t g_memt[(size_t)2048 * TILE_U32];    // memory tensor, tile format fp16
__device__ float g_pre[3 * NSEQ * DMODEL];              // [ns | nt | q]
__device__ float g_qh[NSEQ * 1024];                     // [n][h][c]
__device__ float g_x1[NSEQ * DMODEL];
__device__ float g_h[512 * 2048];                       // ffn hidden (fp32)
__device__ float g_ffp[16 * 512 * DMODEL];              // ffn split-K partials
__device__ float g_bcat[3 * DMODEL];                    // packed pre biases
__device__ uint32_t g_wsw[5 * TILE_U32];                // pre-swizzled fp16 weights

__device__ __forceinline__ float warp_sum(float v) {
#pragma unroll
    for (int o = 16; o; o >>= 1) v += __shfl_xor_sync(0xffffffffu, v, o);
    return v;
}
__device__ __forceinline__ float warp_max(float v) {
#pragma unroll
    for (int o = 16; o; o >>= 1) v = fmaxf(v, __shfl_xor_sync(0xffffffffu, v, o));
    return v;
}
__device__ __forceinline__ uint32_t smem_u32(const void* p) {
    uint32_t a;
    asm("{ .reg .u64 t; cvta.to.shared.u64 t, %1; cvt.u32.u64 %0, t; }" : "=r"(a) : "l"(p));
    return a;
}
__device__ __forceinline__ void mma_f16(float* c, const uint32_t* a, const uint32_t* b) {
    asm volatile(
        "mma.sync.aligned.m16n8k16.row.col.f32.f16.f16.f32 "
        "{%0,%1,%2,%3}, {%4,%5,%6,%7}, {%8,%9}, {%0,%1,%2,%3};"
        : "+f"(c[0]), "+f"(c[1]), "+f"(c[2]), "+f"(c[3])
        : "r"(a[0]), "r"(a[1]), "r"(a[2]), "r"(a[3]), "r"(b[0]), "r"(b[1]));
}
#define LDSM4(r0, r1, r2, r3, addr)                                                     \
    asm volatile("ldmatrix.sync.aligned.m8n8.x4.shared.b16 {%0,%1,%2,%3}, [%4];"        \
        : "=r"(r0), "=r"(r1), "=r"(r2), "=r"(r3) : "r"(addr))
#define LDSM2(r0, r1, addr)                                                             \
    asm volatile("ldmatrix.sync.aligned.m8n8.x2.shared.b16 {%0,%1}, [%2];"              \
        : "=r"(r0), "=r"(r1) : "r"(addr))
#define LDSM4T(r0, r1, r2, r3, addr)                                                    \
    asm volatile("ldmatrix.sync.aligned.m8n8.x4.trans.shared.b16 {%0,%1,%2,%3}, [%4];"  \
        : "=r"(r0), "=r"(r1), "=r"(r2), "=r"(r3) : "r"(addr))
#define LDSM2T(r0, r1, addr)                                                            \
    asm volatile("ldmatrix.sync.aligned.m8n8.x2.trans.shared.b16 {%0,%1}, [%2];"        \
        : "=r"(r0), "=r"(r1) : "r"(addr))
#define CP16(dst, src)                                                                  \
    asm volatile("cp.async.ca.shared.global [%0], [%1], 16;" :: "r"(dst), "l"(src) : "memory")
#define CP_COMMIT() asm volatile("cp.async.commit_group;" ::: "memory")
#define CP_WAIT()   asm volatile("cp.async.wait_group 0;" ::: "memory")

__device__ __forceinline__ uint32_t pack_h2(float a, float b) {
    __half2 p = __floats2half2_rn(a, b);
    return *(uint32_t*)&p;
}

// smem maps
#define A_OFF  0
#define B1_OFF 34816
#define B2_OFF 69632
#define PS_OFF 104448
#define PQ_OFF 106496
#define GSMEM  108544
#define TSMEM  69632

__device__ __forceinline__ void copy_tile_async(const uint32_t* __restrict__ src,
                                                uint32_t dst_s, int t) {
#pragma unroll
    for (int j = 0; j < 9; j++) {
        int idx = t + j * 256;
        if (idx < 2176) CP16(dst_s + idx * 16, (const char*)src + idx * 16);
    }
}
__device__ __forceinline__ void load_atile(const float* __restrict__ At, int lda,
                                           uint32_t* Ah, int t) {
#pragma unroll
    for (int j = 0; j < 16; j++) {
        int idx = t + j * 256;
        int row = idx >> 5, c4 = (idx & 31) * 4;
        float4 v = *(const float4*)(At + (size_t)row * lda + c4);
        *(uint2*)&Ah[row * 68 + (c4 >> 1)] =
            make_uint2(pack_h2(v.x, v.y), pack_h2(v.z, v.w));
    }
}
__device__ __forceinline__ void load_btile(const float* __restrict__ Wt, int ldw,
                                           uint32_t* Bh, int t) {
#pragma unroll
    for (int j = 0; j < 32; j++) {
        int e = t + j * 256;
        int kp = e >> 7, n = e & 127;
        Bh[n * 68 + kp] = pack_h2(Wt[(size_t)(2 * kp) * ldw + n],
                                  Wt[(size_t)(2 * kp + 1) * ldw + n]);
    }
}

// fp16 MMA mainloop over K=128: 8 warps, warp tile 64(m) x 32(n)
__device__ __forceinline__ void mma_loop(uint32_t aBase, uint32_t bBase,
                                         int wm, int wn, int lane, float acc[4][4][4]) {
    const uint32_t aoff = (uint32_t)((lane & 15) * 272 + (lane >> 4) * 16);
    const uint32_t boff = (uint32_t)(((lane >> 4) * 8 + (lane & 7)) * 272
                                     + ((lane >> 3) & 1) * 16);
    uint32_t addrA[4], addrB[2];
#pragma unroll
    for (int mt = 0; mt < 4; mt++) addrA[mt] = aBase + (wm * 64 + mt * 16) * 272 + aoff;
#pragma unroll
    for (int p = 0; p < 2; p++)    addrB[p] = bBase + (wn * 32 + p * 16) * 272 + boff;
#pragma unroll
    for (int mt = 0; mt < 4; mt++)
#pragma unroll
        for (int nt = 0; nt < 4; nt++)
#pragma unroll
            for (int q = 0; q < 4; q++) acc[mt][nt][q] = 0.f;
#pragma unroll
    for (int ks = 0; ks < 8; ks++) {
        uint32_t ah[4][4], bh[4][2];
#pragma unroll
        for (int mt = 0; mt < 4; mt++)
            LDSM4(ah[mt][0], ah[mt][1], ah[mt][2], ah[mt][3], addrA[mt] + ks * 32);
        LDSM4(bh[0][0], bh[0][1], bh[1][0], bh[1][1], addrB[0] + ks * 32);
        LDSM4(bh[2][0], bh[2][1], bh[3][0], bh[3][1], addrB[1] + ks * 32);
#pragma unroll
        for (int mt = 0; mt < 4; mt++)
#pragma unroll
            for (int nt = 0; nt < 4; nt++)
                mma_f16(acc[mt][nt], ah[mt], bh[nt]);
    }
}

// per-row mean/rstd across 128 cols (256-thread version)
__device__ __forceinline__ void row_stats(float acc[4][4][4], float* ps, float* pq,
                                          int wm, int wn, int gid, int lid,
                                          float mean[8], float rstd[8]) {
    float s8[8], q8[8];
#pragma unroll
    for (int mt = 0; mt < 4; mt++) {
        float sl = 0, ql = 0, sh = 0, qh = 0;
#pragma unroll
        for (int nt = 0; nt < 4; nt++) {
            sl += acc[mt][nt][0] + acc[mt][nt][1];
            ql += acc[mt][nt][0]*acc[mt][nt][0] + acc[mt][nt][1]*acc[mt][nt][1];
            sh += acc[mt][nt][2] + acc[mt][nt][3];
            qh += acc[mt][nt][2]*acc[mt][nt][2] + acc[mt][nt][3]*acc[mt][nt][3];
        }
        s8[mt*2] = sl; q8[mt*2] = ql; s8[mt*2+1] = sh; q8[mt*2+1] = qh;
    }
#pragma unroll
    for (int i = 0; i < 8; i++) {
        s8[i] += __shfl_xor_sync(0xffffffffu, s8[i], 1);
        s8[i] += __shfl_xor_sync(0xffffffffu, s8[i], 2);
        q8[i] += __shfl_xor_sync(0xffffffffu, q8[i], 1);
        q8[i] += __shfl_xor_sync(0xffffffffu, q8[i], 2);
    }
    __syncthreads();
    if (lid == 0) {
#pragma unroll
        for (int mt = 0; mt < 4; mt++) {
            int r0 = wm * 64 + mt * 16 + gid;
            ps[r0 * 4 + wn] = s8[mt*2];   pq[r0 * 4 + wn] = q8[mt*2];
            ps[(r0+8)*4 + wn] = s8[mt*2+1]; pq[(r0+8)*4 + wn] = q8[mt*2+1];
        }
    }
    __syncthreads();
#pragma unroll
    for (int mt = 0; mt < 4; mt++)
#pragma unroll
        for (int hh = 0; hh < 2; hh++) {
            int r = wm * 64 + mt * 16 + gid + hh * 8;
            float4 a = *(float4*)&ps[r * 4];
            float4 b = *(float4*)&pq[r * 4];
            float m = (a.x + a.y + a.z + a.w) * (1.f/128.f);
            float v = (b.x + b.y + b.z + b.w) * (1.f/128.f) - m * m;
            mean[mt*2+hh] = m; rstd[mt*2+hh] = rsqrtf(v + LN_EPS);
        }
}

// ============ weight pre-pack: 5 tiles -> swizzled fp16 ============
__global__ void k_wpack(const float* __restrict__ w1, const float* __restrict__ w2,
                        const float* __restrict__ ws, const float* __restrict__ wt,
                        const float* __restrict__ wqp, const float* __restrict__ bm,
                        const float* __restrict__ bq2) {
    const int tile = blockIdx.x, t = threadIdx.x;
    const float* src = (tile == 0) ? w1 : (tile == 1) ? w2 : (tile == 2) ? ws
                     : (tile == 3) ? wt : wqp;
    uint32_t* dst = g_wsw + (size_t)tile * TILE_U32;
#pragma unroll
    for (int j = 0; j < 32; j++) {
        int e = t + j * 256;
        int kp = e >> 7, n = e & 127;
        dst[n * 68 + kp] = pack_h2(src[(2 * kp) * 128 + n], src[(2 * kp + 1) * 128 + n]);
    }
    if (tile == 0 && t < 128) {
        g_bcat[t] = bm[t]; g_bcat[128 + t] = 0.f; g_bcat[256 + t] = bq2[t];
    }
}

// ============ pre GEMM (tiles 2..4) ============
__global__ __launch_bounds__(256, 2) void k_tileA(
    const float* __restrict__ A,
    float* __restrict__ C, const float* __restrict__ bias) {
    extern __shared__ char sm[];
    uint32_t* Ah = (uint32_t*)(sm + A_OFF);
    const int t = threadIdx.x;
    const float* At = A + (size_t)blockIdx.x * 16384;
    const float* bt = bias + blockIdx.y * 128;
    float* Ct = C + (size_t)blockIdx.x * 16384 + (size_t)blockIdx.y * 65536;

    copy_tile_async(g_wsw + (size_t)(2 + blockIdx.y) * TILE_U32, smem_u32(sm) + B1_OFF, t);
    CP_COMMIT();
    load_atile(At, 128, Ah, t);
    CP_WAIT();
    __syncthreads();

    const int w = t >> 5, lane = t & 31, wm = w >> 2, wn = w & 3;
    const int gid = lane >> 2, lid = lane & 3;
    const uint32_t sb = smem_u32(sm);
    float acc[4][4][4];
    mma_loop(sb + A_OFF, sb + B1_OFF, wm, wn, lane, acc);

#pragma unroll
    for (int nt = 0; nt < 4; nt++) {
        int cc = wn * 32 + nt * 8 + lid * 2;
        float2 bb = *(const float2*)&bt[cc];
#pragma unroll
        for (int mt = 0; mt < 4; mt++) {
            int r0 = wm * 64 + mt * 16 + gid;
            *(float2*)&Ct[r0 * 128 + cc] =
                make_float2(acc[mt][nt][0] + bb.x, acc[mt][nt][1] + bb.y);
            *(float2*)&Ct[(r0 + 8) * 128 + cc] =
                make_float2(acc[mt][nt][2] + bb.x, acc[mt][nt][3] + bb.y);
        }
    }
}

// ============ generic tile GEMM (gmem weights): FFN ============
__global__ __launch_bounds__(256, 2) void k_tile(
    const float* __restrict__ A, int lda, int aXstep, int aYstep,
    const float* __restrict__ W, int ldw, int wYstep,
    float* __restrict__ C, int ldc, int cXstep, int cYstep,
    const float* __restrict__ bias, int bYstep, int relu) {
    extern __shared__ char sm[];
    uint32_t* Ah = (uint32_t*)(sm + A_OFF);
    uint32_t* Bh = (uint32_t*)(sm + B1_OFF);
    const int t = threadIdx.x;
    const float* At = A + (size_t)blockIdx.x * aXstep + (size_t)blockIdx.y * aYstep;
    const float* Wt = W + (size_t)blockIdx.y * wYstep;
    float* Ct = C + (size_t)blockIdx.x * cXstep + (size_t)blockIdx.y * cYstep;
    const float* bt = bias ? bias + (size_t)blockIdx.y * bYstep : nullptr;

    load_btile(Wt, ldw, Bh, t);
    load_atile(At, lda, Ah, t);
    __syncthreads();

    const int w = t >> 5, lane = t & 31, wm = w >> 2, wn = w & 3;
    const int gid = lane >> 2, lid = lane & 3;
    const uint32_t sb = smem_u32(sm);
    float acc[4][4][4];
    mma_loop(sb + A_OFF, sb + B1_OFF, wm, wn, lane, acc);

#pragma unroll
    for (int nt = 0; nt < 4; nt++) {
        int cc = wn * 32 + nt * 8 + lid * 2;
        float2 bb = bt ? *(const float2*)&bt[cc] : make_float2(0.f, 0.f);
#pragma unroll
        for (int mt = 0; mt < 4; mt++) {
            int r0 = wm * 64 + mt * 16 + gid;
            float2 o0 = make_float2(acc[mt][nt][0] + bb.x, acc[mt][nt][1] + bb.y);
            float2 o1 = make_float2(acc[mt][nt][2] + bb.x, acc[mt][nt][3] + bb.y);
            if (relu) {
                o0.x = fmaxf(o0.x, 0.f); o0.y = fmaxf(o0.y, 0.f);
                o1.x = fmaxf(o1.x, 0.f); o1.y = fmaxf(o1.y, 0.f);
            }
            *(float2*)&Ct[(size_t)r0 * ldc + cc] = o0;
            *(float2*)&Ct[(size_t)(r0 + 8) * ldc + cc] = o1;
        }
    }
}

// ============ qh precompute ============
#define QH_SMEM 68096
__global__ __launch_bounds__(256) void k_qh(const float* __restrict__ wk) {
    extern __shared__ float wsT[];              // [128 k][133]
    __shared__ float qs[4][128];
    const int t = threadIdx.x;
    for (int i = t; i < 16384; i += 256) {
        int c = i >> 7, k = i & 127;
        wsT[k * 133 + c] = wk[i] * 0.25f;
    }
    for (int i = t; i < 512; i += 256) {
        int j = i >> 7, c = i & 127;
        qs[j][c] = g_pre[2 * 65536 + (blockIdx.x * 4 + j) * 128 + c];
    }
    __syncthreads();
    const int c = t & 127, hb = (t >> 7) * 4;
#pragma unroll
    for (int j = 0; j < 4; j++) {
        int n = blockIdx.x * 4 + j;
#pragma unroll
        for (int ho = 0; ho < 4; ho++) {
            int h = hb + ho;
            float a = 0.f;
#pragma unroll
            for (int dh = 0; dh < 16; dh++)
                a += wsT[(h * 16 + dh) * 133 + c] * qs[j][h * 16 + dh];
            g_qh[n * 1024 + h * 128 + c] = a;
        }
    }
}

// ============ persistent fused double GEMM (256 thr, 64x32 tile) ============
__global__ __launch_bounds__(256, 2) void k_fused(
    const float* __restrict__ edge,
    const float* __restrict__ g1m, const float* __restrict__ b1m,
    const float* __restrict__ bpe,
    const float* __restrict__ gpe, const float* __restrict__ bpe_ln,
    const float* __restrict__ gle, const float* __restrict__ ble,
    float* __restrict__ out_edge) {
    extern __shared__ char sm[];
    uint32_t* A  = (uint32_t*)(sm + A_OFF);
    uint32_t* B1 = (uint32_t*)(sm + B1_OFF);
    float* ps = (float*)(sm + PS_OFF);
    float* pq = (float*)(sm + PQ_OFF);
    const int t = threadIdx.x;
    const uint32_t sb = smem_u32(sm);

    const int w = t >> 5, lane = t & 31, wm = w >> 2, wn = w & 3;
    const int gid = lane >> 2, lid = lane & 3;
    int cc[4];
#pragma unroll
    for (int nt = 0; nt < 4; nt++) cc[nt] = wn * 32 + nt * 8 + lid * 2;

    // W2 staged once per CTA (persists in B2 for all tiles)
    copy_tile_async(g_wsw + TILE_U32, sb + B2_OFF, t);

    for (int b = blockIdx.x; b < 2048; b += gridDim.x) {
        // W1 re-staged each tile (B1 slot is recycled as the memory tile below);
        // overlapped with the A-tile load+convert.
        copy_tile_async(g_wsw, sb + B1_OFF, t);
        CP_COMMIT();
        load_atile(edge + (size_t)b * 16384, 128, A, t);
        CP_WAIT();
        __syncthreads();

        float acc[4][4][4];

        // ---- GEMM1: edge @ W1 ----
        mma_loop(sb + A_OFF, sb + B1_OFF, wm, wn, lane, acc);

        // ---- epilogue 1: +ns+nt, LN, relu -> B1 (fp16 tile) ----
        {
            const int s_tile = b >> 2, nbase = (b & 3) * 128;
#pragma unroll
            for (int nt = 0; nt < 4; nt++) {
                float2 ntv = *(const float2*)&g_pre[65536 + s_tile * 128 + cc[nt]];
#pragma unroll
                for (int mt = 0; mt < 4; mt++) {
                    int r0 = wm * 64 + mt * 16 + gid;
                    float2 n0 = *(const float2*)&g_pre[(nbase + r0) * 128 + cc[nt]];
                    float2 n1 = *(const float2*)&g_pre[(nbase + r0 + 8) * 128 + cc[nt]];
                    acc[mt][nt][0] += n0.x + ntv.x; acc[mt][nt][1] += n0.y + ntv.y;
                    acc[mt][nt][2] += n1.x + ntv.x; acc[mt][nt][3] += n1.y + ntv.y;
                }
            }
            float mean[8], rstd[8];
            row_stats(acc, ps, pq, wm, wn, gid, lid, mean, rstd);
#pragma unroll
            for (int nt = 0; nt < 4; nt++) {
                float2 gv = *(const float2*)&g1m[cc[nt]];
                float2 bv2 = *(const float2*)&b1m[cc[nt]];
#pragma unroll
                for (int mt = 0; mt < 4; mt++) {
                    int r0 = wm * 64 + mt * 16 + gid;
                    float o0x = fmaxf((acc[mt][nt][0]-mean[mt*2])*rstd[mt*2]*gv.x + bv2.x, 0.f);
                    float o0y = fmaxf((acc[mt][nt][1]-mean[mt*2])*rstd[mt*2]*gv.y + bv2.y, 0.f);
                    float o1x = fmaxf((acc[mt][nt][2]-mean[mt*2+1])*rstd[mt*2+1]*gv.x + bv2.x, 0.f);
                    float o1y = fmaxf((acc[mt][nt][3]-mean[mt*2+1])*rstd[mt*2+1]*gv.y + bv2.y, 0.f);
                    B1[r0 * 68 + (cc[nt] >> 1)] = pack_h2(o0x, o0y);
                    B1[(r0 + 8) * 68 + (cc[nt] >> 1)] = pack_h2(o1x, o1y);
                }
            }
        }
        __syncthreads();   // B1 = memory tile (fp16)

        // ---- coalesced bulk store of memory tile to gmem (tile format) ----
        {
            uint4* dst = (uint4*)(g_memt + (size_t)b * TILE_U32);
            const uint4* srcB = (const uint4*)B1;
#pragma unroll
            for (int j = 0; j < 9; j++) {
                int idx = t + j * 256;
                if (idx < 2176) dst[idx] = srcB[idx];
            }
        }

        // ---- GEMM2: memory @ W2 ----
        mma_loop(sb + B1_OFF, sb + B2_OFF, wm, wn, lane, acc);

        // ---- epilogue 2 ----
        {
#pragma unroll
            for (int nt = 0; nt < 4; nt++) {
                float2 bp = *(const float2*)&bpe[cc[nt]];
#pragma unroll
                for (int mt = 0; mt < 4; mt++) {
                    acc[mt][nt][0] += bp.x; acc[mt][nt][1] += bp.y;
                    acc[mt][nt][2] += bp.x; acc[mt][nt][3] += bp.y;
                }
            }
            float mean[8], rstd[8];
            row_stats(acc, ps, pq, wm, wn, gid, lid, mean, rstd);
#pragma unroll
            for (int nt = 0; nt < 4; nt++) {
                float2 g1 = *(const float2*)&gpe[cc[nt]];
                float2 b1 = *(const float2*)&bpe_ln[cc[nt]];
#pragma unroll
                for (int mt = 0; mt < 4; mt++) {
                    int r0 = wm * 64 + mt * 16 + gid;
                    float2 e0 = __half22float2(*(__half2*)&A[r0 * 68 + (cc[nt] >> 1)]);
                    float2 e1 = __half22float2(*(__half2*)&A[(r0 + 8) * 68 + (cc[nt] >> 1)]);
                    acc[mt][nt][0] = e0.x + fmaxf((acc[mt][nt][0]-mean[mt*2])*rstd[mt*2]*g1.x + b1.x, 0.f);
                    acc[mt][nt][1] = e0.y + fmaxf((acc[mt][nt][1]-mean[mt*2])*rstd[mt*2]*g1.y + b1.y, 0.f);
                    acc[mt][nt][2] = e1.x + fmaxf((acc[mt][nt][2]-mean[mt*2+1])*rstd[mt*2+1]*g1.x + b1.x, 0.f);
                    acc[mt][nt][3] = e1.y + fmaxf((acc[mt][nt][3]-mean[mt*2+1])*rstd[mt*2+1]*g1.y + b1.y, 0.f);
                }
            }
            row_stats(acc, ps, pq, wm, wn, gid, lid, mean, rstd);
            float* orow = out_edge + (size_t)b * 16384;
#pragma unroll
            for (int nt = 0; nt < 4; nt++) {
                float2 g2 = *(const float2*)&gle[cc[nt]];
                float2 b2 = *(const float2*)&ble[cc[nt]];
#pragma unroll
                for (int mt = 0; mt < 4; mt++) {
                    int r0 = wm * 64 + mt * 16 + gid;
                    float2 o0, o1;
                    o0.x = (acc[mt][nt][0]-mean[mt*2])*rstd[mt*2]*g2.x + b2.x;
                    o0.y = (acc[mt][nt][1]-mean[mt*2])*rstd[mt*2]*g2.y + b2.y;
                    o1.x = (acc[mt][nt][2]-mean[mt*2+1])*rstd[mt*2+1]*g2.x + b2.x;
                    o1.y = (acc[mt][nt][3]-mean[mt*2+1])*rstd[mt*2+1]*g2.y + b2.y;
                    *(float2*)&orow[r0 * 128 + cc[nt]] = o0;
                    *(float2*)&orow[(r0 + 8) * 128 + cc[nt]] = o1;
                }
            }
        }
        // row_stats' internal barriers above guarantee A and B1 are fully
        // consumed by all threads before the next iteration's loads.
    }
}

// ============ fused attention + out1 (512 threads, MMA both phases) ============
#define MH_OFF   0
#define QB_OFF   139264
#define ATT_OFF  141440
#define MK_OFF   157824
#define ATT2_OFF 158336
#define RPA_OFF  166528
#define RPB_OFF  170624
#define CS_OFF   174720
#define RS_OFF   175232
#define ATT_SMEM 175360
__global__ __launch_bounds__(512) void k_attn2(
    const unsigned char* __restrict__ mask,
    const float* __restrict__ wv, const float* __restrict__ bv,
    const float* __restrict__ node, const float* __restrict__ wo,
    const float* __restrict__ bo, const float* __restrict__ g2,
    const float* __restrict__ b2) {
    extern __shared__ char sm[];
    __half* mh = (__half*)(sm + MH_OFF);
    __half* qb = (__half*)(sm + QB_OFF);
    float* att = (float*)(sm + ATT_OFF);
    unsigned char* mk = (unsigned char*)(sm + MK_OFF);
    __half* att2 = (__half*)(sm + ATT2_OFF);
    const int n = blockIdx.x, t = threadIdx.x, w = t >> 5, lane = t & 31;
    const uint32_t sb = smem_u32(sm);

    for (int i = t; i < 1024; i += 512) {
        int h = i >> 7, c = i & 127;
        qb[h * 136 + c] = __float2half_rn(g_qh[n * 1024 + i]);
    }
    mk[t & 511] = mask[n * 512 + (t & 511)];
    {
        const int nhi = n >> 7, row = n & 127;
        const uint32_t* base = g_memt + (size_t)row * 68 + (size_t)nhi * TILE_U32;
#pragma unroll 4
        for (int j = 0; j < 16; j++) {
            int idx = t + j * 512;
            int s = idx >> 4, k4 = idx & 15;
            uint4 v = *(const uint4*)(base + (size_t)s * (4 * TILE_U32) + k4 * 4);
            *(uint4*)&mh[s * 136 + k4 * 8] = v;
        }
    }
    __syncthreads();

    // ---- scores via MMA: warp w covers s in [w*32, w*32+32) ----
    {
        const int l2 = lane & 15;
        const uint32_t aoffA = (uint32_t)((lane & 15) * 272 + (lane >> 4) * 16);
        const uint32_t qaddr = sb + QB_OFF + (uint32_t)((l2 & 7) * 272 + ((l2 >> 3) & 1) * 16);
        float acc[2][4];
#pragma unroll
        for (int mt = 0; mt < 2; mt++)
#pragma unroll
            for (int q = 0; q < 4; q++) acc[mt][q] = 0.f;
#pragma unroll
        for (int ks = 0; ks < 8; ks++) {
            uint32_t bq[2];
            LDSM2(bq[0], bq[1], qaddr + ks * 32);
#pragma unroll
            for (int mt = 0; mt < 2; mt++) {
                uint32_t a[4];
                LDSM4(a[0], a[1], a[2], a[3],
                      sb + MH_OFF + (w * 32 + mt * 16) * 272 + aoffA + ks * 32);
                mma_f16(acc[mt], a, bq);
            }
        }
        const int gid = lane >> 2, lid = lane & 3;
#pragma unroll
        for (int mt = 0; mt < 2; mt++) {
            int s = w * 32 + mt * 16 + gid;
            att[(2 * lid) * 512 + s]     = acc[mt][0];
            att[(2 * lid + 1) * 512 + s] = acc[mt][1];
            att[(2 * lid) * 512 + s + 8]     = acc[mt][2];
            att[(2 * lid + 1) * 512 + s + 8] = acc[mt][3];
        }
    }
    __syncthreads();

    // ---- softmax per head, apply mask ----
    if (w < 8) {
        const int h = w;
        float sc[16];
        float mx = -3.402823466e38f;
#pragma unroll
        for (int i = 0; i < 16; i++) {
            int s = lane + i * 32;
            sc[i] = mk[s] ? -3.402823466e38f : att[h * 512 + s];
            mx = fmaxf(mx, sc[i]);
        }
        mx = warp_max(mx);
        float sum = 0.f;
#pragma unroll
        for (int i = 0; i < 16; i++) { sc[i] = __expf(sc[i] - mx); sum += sc[i]; }
        sum = warp_sum(sum);
        float inv = 1.f / sum;
#pragma unroll
        for (int i = 0; i < 16; i++) att[h * 512 + lane + i * 32] = sc[i] * inv;
    }
    __syncthreads();

    // ---- convert att [h][s] fp32 -> att2 [s][8h] fp16 ----
    {
        int s = t;
        uint32_t p0 = pack_h2(att[0 * 512 + s], att[1 * 512 + s]);
        uint32_t p1 = pack_h2(att[2 * 512 + s], att[3 * 512 + s]);
        uint32_t p2 = pack_h2(att[4 * 512 + s], att[5 * 512 + s]);
        uint32_t p3 = pack_h2(att[6 * 512 + s], att[7 * 512 + s]);
        *(uint4*)&att2[s * 8] = make_uint4(p0, p1, p2, p3);
    }
    __syncthreads();

    // ---- weighted sum via MMA: r(c x h) = mem^T @ att ----
    {
        const int ctile = w >> 1, khalf = w & 1;
        const uint32_t a_base = sb + MH_OFF
            + (uint32_t)((khalf * 256 + (lane & 7) + ((lane >> 4) & 1) * 8) * 272
                         + ctile * 32 + ((lane >> 3) & 1) * 16);
        const uint32_t b_base = sb + ATT2_OFF
            + (uint32_t)((khalf * 256 + (lane & 15)) * 16);
        float accw[4] = {0.f, 0.f, 0.f, 0.f};
#pragma unroll
        for (int kk = 0; kk < 16; kk++) {
            uint32_t a[4], b[2];
            LDSM4T(a[0], a[1], a[2], a[3], a_base + kk * 16 * 272);
            LDSM2T(b[0], b[1], b_base + kk * 256);
            mma_f16(accw, a, b);
        }
        float* rp = (float*)(sm + (khalf ? RPB_OFF : RPA_OFF));
        const int gid = lane >> 2, lid = lane & 3;
        int c0 = ctile * 16 + gid, h0 = 2 * lid;
        rp[c0 * 8 + h0] = accw[0];       rp[c0 * 8 + h0 + 1] = accw[1];
        rp[(c0 + 8) * 8 + h0] = accw[2]; rp[(c0 + 8) * 8 + h0 + 1] = accw[3];
    }
    __syncthreads();

    // ---- ctx = r @ wv + bv ----
    float* rpA = (float*)(sm + RPA_OFF);
    float* rpB = (float*)(sm + RPB_OFF);
    float* cs = (float*)(sm + CS_OFF);
    if (t < 128) {
        int h = t >> 4;
        float a = bv[t];
#pragma unroll 8
        for (int c = 0; c < 128; c++)
            a += (rpA[c * 8 + h] + rpB[c * 8 + h]) * wv[c * 128 + t];
        cs[t] = a;
    }
    __syncthreads();

    // ---- x1 = LN(node + ctx @ wo + bo) ----
    float* rsum = (float*)(sm + RS_OFF);
    float* rsq  = (float*)(sm + RS_OFF + 64);
    float aval = 0.f;
    if (t < 128) {
        aval = bo[t] + node[n * 128 + t];
#pragma unroll 8
        for (int c = 0; c < 128; c++) aval += cs[c] * wo[c * 128 + t];
        float s1 = warp_sum(aval), s2 = warp_sum(aval * aval);
        if ((t & 31) == 0) { rsum[t >> 5] = s1; rsq[t >> 5] = s2; }
    }
    __syncthreads();
    if (t < 128) {
        float sum = rsum[0] + rsum[1] + rsum[2] + rsum[3];
        float sq  = rsq[0] + rsq[1] + rsq[2] + rsq[3];
        float mean = sum * (1.f / 128.f);
        float rs = rsqrtf(sq * (1.f / 128.f) - mean * mean + LN_EPS);
        g_x1[n * 128 + t] = (aval - mean) * rs * g2[t] + b2[t];
    }
}

// ============ final: out_x = LN(x1 + sum_k ffp[k] + b2) ============
__global__ void k_fin(const float* __restrict__ b2, const float* __restrict__ g3,
                      const float* __restrict__ b3, float* __restrict__ out_x) {
    int row = blockIdx.x, d = threadIdx.x;
    __shared__ float rsum[4], rsq[4];
    float v = g_x1[row * 128 + d] + b2[d];
#pragma unroll
    for (int k = 0; k < 16; k++) v += g_ffp[k * 65536 + row * 128 + d];
    float s1 = warp_sum(v), s2 = warp_sum(v * v);
    if ((d & 31) == 0) { rsum[d >> 5] = s1; rsq[d >> 5] = s2; }
    __syncthreads();
    float sum = rsum[0] + rsum[1] + rsum[2] + rsum[3];
    float sq = rsq[0] + rsq[1] + rsq[2] + rsq[3];
    float mean = sum * (1.f / 128.f);
    float rs = rsqrtf(sq * (1.f / 128.f) - mean * mean + LN_EPS);
    out_x[row * 128 + d] = (v - mean) * rs * g3[d] + b3[d];
}

extern "C" void kernel_launch(void* const* d_in, const int* in_sizes, int n_in,
                              void* d_out, int out_size) {
    (void)in_sizes; (void)n_in; (void)out_size;
    const float* node     = (const float*)d_in[0];
    const float* edge     = (const float*)d_in[1];
    const unsigned char* mask = (const unsigned char*)d_in[2];
    const float* w_mem_e  = (const float*)d_in[3];
    const float* w_mem_s  = (const float*)d_in[4];
    const float* w_mem_t  = (const float*)d_in[5];
    const float* b_mem    = (const float*)d_in[6];
    const float* g_ln_mem = (const float*)d_in[7];
    const float* b_ln_mem = (const float*)d_in[8];
    const float* w_pe     = (const float*)d_in[9];
    const float* b_pe     = (const float*)d_in[10];
    const float* g_ln_pe  = (const float*)d_in[11];
    const float* b_ln_pe  = (const float*)d_in[12];
    const float* g_ln_edge= (const float*)d_in[13];
    const float* b_ln_edge= (const float*)d_in[14];
    const float* wq       = (const float*)d_in[15];
    const float* bq       = (const float*)d_in[16];
    const float* wk       = (const float*)d_in[17];
    /* bk (d_in[18]) provably drops out of softmax */
    const float* wv       = (const float*)d_in[19];
    const float* bv       = (const float*)d_in[20];
    const float* wo       = (const float*)d_in[21];
    const float* bo       = (const float*)d_in[22];
    const float* g_ln2    = (const float*)d_in[23];
    const float* b_ln2    = (const float*)d_in[24];
    const float* w_ff1    = (const float*)d_in[25];
    const float* b_ff1    = (const float*)d_in[26];
    const float* w_ff2    = (const float*)d_in[27];
    const float* b_ff2    = (const float*)d_in[28];
    const float* g_ln3    = (const float*)d_in[29];
    const float* b_ln3    = (const float*)d_in[30];

    float* out_x = (float*)d_out;
    float* out_edge = (float*)d_out + NSEQ * DMODEL;

    cudaFuncSetAttribute(k_fused, cudaFuncAttributeMaxDynamicSharedMemorySize, GSMEM);
    cudaFuncSetAttribute(k_tileA, cudaFuncAttributeMaxDynamicSharedMemorySize, TSMEM);
    cudaFuncSetAttribute(k_tile, cudaFuncAttributeMaxDynamicSharedMemorySize, TSMEM);
    cudaFuncSetAttribute(k_attn2, cudaFuncAttributeMaxDynamicSharedMemorySize, ATT_SMEM);
    cudaFuncSetAttribute(k_qh, cudaFuncAttributeMaxDynamicSharedMemorySize, QH_SMEM);

    float* d_pre;  cudaGetSymbolAddress((void**)&d_pre, g_pre);
    float* d_bcat; cudaGetSymbolAddress((void**)&d_bcat, g_bcat);
    float* d_h;    cudaGetSymbolAddress((void**)&d_h, g_h);
    float* d_ffp;  cudaGetSymbolAddress((void**)&d_ffp, g_ffp);
    float* d_x1;   cudaGetSymbolAddress((void**)&d_x1, g_x1);

    k_wpack<<<5, 256>>>(w_mem_e, w_pe, w_mem_s, w_mem_t, wq, b_mem, bq);
    // [ns|nt|q] = node @ [w_mem_s|w_mem_t|wq] + [b_mem|0|bq]
    k_tileA<<<dim3(4, 3), 256, TSMEM>>>(node, d_pre, d_bcat);
    k_qh<<<128, 256, QH_SMEM>>>(wk);
    // memory (fp16 tile format) + edge_new in one pass (persistent, 1 wave)
    k_fused<<<296, 256, GSMEM>>>(edge, g_ln_mem, b_ln_mem,
                                 b_pe, g_ln_pe, b_ln_pe, g_ln_edge, b_ln_edge, out_edge);
    k_attn2<<<512, 512, ATT_SMEM>>>(mask, wv, bv, node, wo, bo, g_ln2, b_ln2);
    // h = relu(x1 @ w1 + b1)
    k_tile<<<dim3(4, 16), 256, TSMEM>>>(d_x1, 128, 16384, 0, w_ff1, 2048, 128,
                                        d_h, 2048, 262144, 128, b_ff1, 128, 1);
    // ffp[k] = h_chunk @ w2_chunk
    k_tile<<<dim3(4, 16), 256, TSMEM>>>(d_h, 2048, 262144, 128, w_ff2, 128, 16384,
                                        d_ffp, 128, 16384, 65536, nullptr, 0, 0);
    k_fin<<<512, 128>>>(b_ff2, g_ln3, b_ln3, out_x);
}

// round 17
// speedup vs baseline: 1.0256x; 1.0256x over previous
#include <cuda_runtime.h>
#include <cuda_fp16.h>
#include <cstdint>

#define NSEQ 512
#define DMODEL 128
#define LN_EPS 1e-5f
#define TILE_U32 8704          // 128 * 68

// ---- scratch (device globals; no runtime allocation) ----
__device__ uint32_t g_memt[(size_t)2048 * TILE_U32];    // memory tensor, tile format fp16
__device__ float g_pre[3 * NSEQ * DMODEL];              // [ns | nt | q]
__device__ float g_qh[NSEQ * 1024];                     // [n][h][c]
__device__ float g_x1[NSEQ * DMODEL];
__device__ float g_h[512 * 2048];                       // ffn hidden (fp32)
__device__ float g_ffp[16 * 512 * DMODEL];              // ffn split-K partials
__device__ float g_bcat[3 * DMODEL];                    // packed pre biases
__device__ uint32_t g_wsw[5 * TILE_U32];                // pre-swizzled fp16 weights

__device__ __forceinline__ float warp_sum(float v) {
#pragma unroll
    for (int o = 16; o; o >>= 1) v += __shfl_xor_sync(0xffffffffu, v, o);
    return v;
}
__device__ __forceinline__ float warp_max(float v) {
#pragma unroll
    for (int o = 16; o; o >>= 1) v = fmaxf(v, __shfl_xor_sync(0xffffffffu, v, o));
    return v;
}
__device__ __forceinline__ uint32_t smem_u32(const void* p) {
    uint32_t a;
    asm("{ .reg .u64 t; cvta.to.shared.u64 t, %1; cvt.u32.u64 %0, t; }" : "=r"(a) : "l"(p));
    return a;
}
__device__ __forceinline__ void mma_f16(float* c, const uint32_t* a, const uint32_t* b) {
    asm volatile(
        "mma.sync.aligned.m16n8k16.row.col.f32.f16.f16.f32 "
        "{%0,%1,%2,%3}, {%4,%5,%6,%7}, {%8,%9}, {%0,%1,%2,%3};"
        : "+f"(c[0]), "+f"(c[1]), "+f"(c[2]), "+f"(c[3])
        : "r"(a[0]), "r"(a[1]), "r"(a[2]), "r"(a[3]), "r"(b[0]), "r"(b[1]));
}
#define LDSM4(r0, r1, r2, r3, addr)                                                     \
    asm volatile("ldmatrix.sync.aligned.m8n8.x4.shared.b16 {%0,%1,%2,%3}, [%4];"        \
        : "=r"(r0), "=r"(r1), "=r"(r2), "=r"(r3) : "r"(addr))
#define LDSM2(r0, r1, addr)                                                             \
    asm volatile("ldmatrix.sync.aligned.m8n8.x2.shared.b16 {%0,%1}, [%2];"              \
        : "=r"(r0), "=r"(r1) : "r"(addr))
#define LDSM4T(r0, r1, r2, r3, addr)                                                    \
    asm volatile("ldmatrix.sync.aligned.m8n8.x4.trans.shared.b16 {%0,%1,%2,%3}, [%4];"  \
        : "=r"(r0), "=r"(r1), "=r"(r2), "=r"(r3) : "r"(addr))
#define LDSM2T(r0, r1, addr)                                                            \
    asm volatile("ldmatrix.sync.aligned.m8n8.x2.trans.shared.b16 {%0,%1}, [%2];"        \
        : "=r"(r0), "=r"(r1) : "r"(addr))
#define CP16(dst, src)                                                                  \
    asm volatile("cp.async.ca.shared.global [%0], [%1], 16;" :: "r"(dst), "l"(src) : "memory")
#define CP_COMMIT() asm volatile("cp.async.commit_group;" ::: "memory")
#define CP_WAIT()   asm volatile("cp.async.wait_group 0;" ::: "memory")

__device__ __forceinline__ uint32_t pack_h2(float a, float b) {
    __half2 p = __floats2half2_rn(a, b);
    return *(uint32_t*)&p;
}

// smem maps
#define A_OFF  0
#define B1_OFF 34816
#define B2_OFF 69632
#define PS_OFF 104448
#define PQ_OFF 106496
#define GSMEM  108544
#define TSMEM  69632

__device__ __forceinline__ void copy_tile_async(const uint32_t* __restrict__ src,
                                                uint32_t dst_s, int t) {
#pragma unroll
    for (int j = 0; j < 9; j++) {
        int idx = t + j * 256;
        if (idx < 2176) CP16(dst_s + idx * 16, (const char*)src + idx * 16);
    }
}
__device__ __forceinline__ void load_atile(const float* __restrict__ At, int lda,
                                           uint32_t* Ah, int t) {
#pragma unroll
    for (int j = 0; j < 16; j++) {
        int idx = t + j * 256;
        int row = idx >> 5, c4 = (idx & 31) * 4;
        float4 v = *(const float4*)(At + (size_t)row * lda + c4);
        *(uint2*)&Ah[row * 68 + (c4 >> 1)] =
            make_uint2(pack_h2(v.x, v.y), pack_h2(v.z, v.w));
    }
}
__device__ __forceinline__ void load_btile(const float* __restrict__ Wt, int ldw,
                                           uint32_t* Bh, int t) {
#pragma unroll
    for (int j = 0; j < 32; j++) {
        int e = t + j * 256;
        int kp = e >> 7, n = e & 127;
        Bh[n * 68 + kp] = pack_h2(Wt[(size_t)(2 * kp) * ldw + n],
                                  Wt[(size_t)(2 * kp + 1) * ldw + n]);
    }
}

// fp16 MMA mainloop over K=128: 8 warps, warp tile 64(m) x 32(n)
__device__ __forceinline__ void mma_loop(uint32_t aBase, uint32_t bBase,
                                         int wm, int wn, int lane, float acc[4][4][4]) {
    const uint32_t aoff = (uint32_t)((lane & 15) * 272 + (lane >> 4) * 16);
    const uint32_t boff = (uint32_t)(((lane >> 4) * 8 + (lane & 7)) * 272
                                     + ((lane >> 3) & 1) * 16);
    uint32_t addrA[4], addrB[2];
#pragma unroll
    for (int mt = 0; mt < 4; mt++) addrA[mt] = aBase + (wm * 64 + mt * 16) * 272 + aoff;
#pragma unroll
    for (int p = 0; p < 2; p++)    addrB[p] = bBase + (wn * 32 + p * 16) * 272 + boff;
#pragma unroll
    for (int mt = 0; mt < 4; mt++)
#pragma unroll
        for (int nt = 0; nt < 4; nt++)
#pragma unroll
            for (int q = 0; q < 4; q++) acc[mt][nt][q] = 0.f;
#pragma unroll
    for (int ks = 0; ks < 8; ks++) {
        uint32_t ah[4][4], bh[4][2];
#pragma unroll
        for (int mt = 0; mt < 4; mt++)
            LDSM4(ah[mt][0], ah[mt][1], ah[mt][2], ah[mt][3], addrA[mt] + ks * 32);
        LDSM4(bh[0][0], bh[0][1], bh[1][0], bh[1][1], addrB[0] + ks * 32);
        LDSM4(bh[2][0], bh[2][1], bh[3][0], bh[3][1], addrB[1] + ks * 32);
#pragma unroll
        for (int mt = 0; mt < 4; mt++)
#pragma unroll
            for (int nt = 0; nt < 4; nt++)
                mma_f16(acc[mt][nt], ah[mt], bh[nt]);
    }
}

// per-row mean/rstd across 128 cols (256-thread version)
__device__ __forceinline__ void row_stats(float acc[4][4][4], float* ps, float* pq,
                                          int wm, int wn, int gid, int lid,
                                          float mean[8], float rstd[8]) {
    float s8[8], q8[8];
#pragma unroll
    for (int mt = 0; mt < 4; mt++) {
        float sl = 0, ql = 0, sh = 0, qh = 0;
#pragma unroll
        for (int nt = 0; nt < 4; nt++) {
            sl += acc[mt][nt][0] + acc[mt][nt][1];
            ql += acc[mt][nt][0]*acc[mt][nt][0] + acc[mt][nt][1]*acc[mt][nt][1];
            sh += acc[mt][nt][2] + acc[mt][nt][3];
            qh += acc[mt][nt][2]*acc[mt][nt][2] + acc[mt][nt][3]*acc[mt][nt][3];
        }
        s8[mt*2] = sl; q8[mt*2] = ql; s8[mt*2+1] = sh; q8[mt*2+1] = qh;
    }
#pragma unroll
    for (int i = 0; i < 8; i++) {
        s8[i] += __shfl_xor_sync(0xffffffffu, s8[i], 1);
        s8[i] += __shfl_xor_sync(0xffffffffu, s8[i], 2);
        q8[i] += __shfl_xor_sync(0xffffffffu, q8[i], 1);
        q8[i] += __shfl_xor_sync(0xffffffffu, q8[i], 2);
    }
    __syncthreads();
    if (lid == 0) {
#pragma unroll
        for (int mt = 0; mt < 4; mt++) {
            int r0 = wm * 64 + mt * 16 + gid;
            ps[r0 * 4 + wn] = s8[mt*2];   pq[r0 * 4 + wn] = q8[mt*2];
            ps[(r0+8)*4 + wn] = s8[mt*2+1]; pq[(r0+8)*4 + wn] = q8[mt*2+1];
        }
    }
    __syncthreads();
#pragma unroll
    for (int mt = 0; mt < 4; mt++)
#pragma unroll
        for (int hh = 0; hh < 2; hh++) {
            int r = wm * 64 + mt * 16 + gid + hh * 8;
            float4 a = *(float4*)&ps[r * 4];
            float4 b = *(float4*)&pq[r * 4];
            float m = (a.x + a.y + a.z + a.w) * (1.f/128.f);
            float v = (b.x + b.y + b.z + b.w) * (1.f/128.f) - m * m;
            mean[mt*2+hh] = m; rstd[mt*2+hh] = rsqrtf(v + LN_EPS);
        }
}

// ============ weight pre-pack: 5 tiles -> swizzled fp16 ============
__global__ void k_wpack(const float* __restrict__ w1, const float* __restrict__ w2,
                        const float* __restrict__ ws, const float* __restrict__ wt,
                        const float* __restrict__ wqp, const float* __restrict__ bm,
                        const float* __restrict__ bq2) {
    const int tile = blockIdx.x, t = threadIdx.x;
    const float* src = (tile == 0) ? w1 : (tile == 1) ? w2 : (tile == 2) ? ws
                     : (tile == 3) ? wt : wqp;
    uint32_t* dst = g_wsw + (size_t)tile * TILE_U32;
#pragma unroll
    for (int j = 0; j < 32; j++) {
        int e = t + j * 256;
        int kp = e >> 7, n = e & 127;
        dst[n * 68 + kp] = pack_h2(src[(2 * kp) * 128 + n], src[(2 * kp + 1) * 128 + n]);
    }
    if (tile == 0 && t < 128) {
        g_bcat[t] = bm[t]; g_bcat[128 + t] = 0.f; g_bcat[256 + t] = bq2[t];
    }
}

// ============ pre GEMM (tiles 2..4) ============
__global__ __launch_bounds__(256, 2) void k_tileA(
    const float* __restrict__ A,
    float* __restrict__ C, const float* __restrict__ bias) {
    extern __shared__ char sm[];
    uint32_t* Ah = (uint32_t*)(sm + A_OFF);
    const int t = threadIdx.x;
    const float* At = A + (size_t)blockIdx.x * 16384;
    const float* bt = bias + blockIdx.y * 128;
    float* Ct = C + (size_t)blockIdx.x * 16384 + (size_t)blockIdx.y * 65536;

    copy_tile_async(g_wsw + (size_t)(2 + blockIdx.y) * TILE_U32, smem_u32(sm) + B1_OFF, t);
    CP_COMMIT();
    load_atile(At, 128, Ah, t);
    CP_WAIT();
    __syncthreads();

    const int w = t >> 5, lane = t & 31, wm = w >> 2, wn = w & 3;
    const int gid = lane >> 2, lid = lane & 3;
    const uint32_t sb = smem_u32(sm);
    float acc[4][4][4];
    mma_loop(sb + A_OFF, sb + B1_OFF, wm, wn, lane, acc);

#pragma unroll
    for (int nt = 0; nt < 4; nt++) {
        int cc = wn * 32 + nt * 8 + lid * 2;
        float2 bb = *(const float2*)&bt[cc];
#pragma unroll
        for (int mt = 0; mt < 4; mt++) {
            int r0 = wm * 64 + mt * 16 + gid;
            *(float2*)&Ct[r0 * 128 + cc] =
                make_float2(acc[mt][nt][0] + bb.x, acc[mt][nt][1] + bb.y);
            *(float2*)&Ct[(r0 + 8) * 128 + cc] =
                make_float2(acc[mt][nt][2] + bb.x, acc[mt][nt][3] + bb.y);
        }
    }
}

// ============ generic tile GEMM (gmem weights): FFN ============
__global__ __launch_bounds__(256, 2) void k_tile(
    const float* __restrict__ A, int lda, int aXstep, int aYstep,
    const float* __restrict__ W, int ldw, int wYstep,
    float* __restrict__ C, int ldc, int cXstep, int cYstep,
    const float* __restrict__ bias, int bYstep, int relu) {
    extern __shared__ char sm[];
    uint32_t* Ah = (uint32_t*)(sm + A_OFF);
    uint32_t* Bh = (uint32_t*)(sm + B1_OFF);
    const int t = threadIdx.x;
    const float* At = A + (size_t)blockIdx.x * aXstep + (size_t)blockIdx.y * aYstep;
    const float* Wt = W + (size_t)blockIdx.y * wYstep;
    float* Ct = C + (size_t)blockIdx.x * cXstep + (size_t)blockIdx.y * cYstep;
    const float* bt = bias ? bias + (size_t)blockIdx.y * bYstep : nullptr;

    load_btile(Wt, ldw, Bh, t);
    load_atile(At, lda, Ah, t);
    __syncthreads();

    const int w = t >> 5, lane = t & 31, wm = w >> 2, wn = w & 3;
    const int gid = lane >> 2, lid = lane & 3;
    const uint32_t sb = smem_u32(sm);
    float acc[4][4][4];
    mma_loop(sb + A_OFF, sb + B1_OFF, wm, wn, lane, acc);

#pragma unroll
    for (int nt = 0; nt < 4; nt++) {
        int cc = wn * 32 + nt * 8 + lid * 2;
        float2 bb = bt ? *(const float2*)&bt[cc] : make_float2(0.f, 0.f);
#pragma unroll
        for (int mt = 0; mt < 4; mt++) {
            int r0 = wm * 64 + mt * 16 + gid;
            float2 o0 = make_float2(acc[mt][nt][0] + bb.x, acc[mt][nt][1] + bb.y);
            float2 o1 = make_float2(acc[mt][nt][2] + bb.x, acc[mt][nt][3] + bb.y);
            if (relu) {
                o0.x = fmaxf(o0.x, 0.f); o0.y = fmaxf(o0.y, 0.f);
                o1.x = fmaxf(o1.x, 0.f); o1.y = fmaxf(o1.y, 0.f);
            }
            *(float2*)&Ct[(size_t)r0 * ldc + cc] = o0;
            *(float2*)&Ct[(size_t)(r0 + 8) * ldc + cc] = o1;
        }
    }
}

// ============ qh precompute ============
#define QH_SMEM 68096
__global__ __launch_bounds__(256) void k_qh(const float* __restrict__ wk) {
    extern __shared__ float wsT[];              // [128 k][133]
    __shared__ float qs[4][128];
    const int t = threadIdx.x;
    for (int i = t; i < 16384; i += 256) {
        int c = i >> 7, k = i & 127;
        wsT[k * 133 + c] = wk[i] * 0.25f;
    }
    for (int i = t; i < 512; i += 256) {
        int j = i >> 7, c = i & 127;
        qs[j][c] = g_pre[2 * 65536 + (blockIdx.x * 4 + j) * 128 + c];
    }
    __syncthreads();
    const int c = t & 127, hb = (t >> 7) * 4;
#pragma unroll
    for (int j = 0; j < 4; j++) {
        int n = blockIdx.x * 4 + j;
#pragma unroll
        for (int ho = 0; ho < 4; ho++) {
            int h = hb + ho;
            float a = 0.f;
#pragma unroll
            for (int dh = 0; dh < 16; dh++)
                a += wsT[(h * 16 + dh) * 133 + c] * qs[j][h * 16 + dh];
            g_qh[n * 1024 + h * 128 + c] = a;
        }
    }
}

// ============ fused double GEMM (256 thr, 64x32 tile) ============
__global__ __launch_bounds__(256, 2) void k_fused(
    const float* __restrict__ edge,
    const float* __restrict__ g1m, const float* __restrict__ b1m,
    const float* __restrict__ bpe,
    const float* __restrict__ gpe, const float* __restrict__ bpe_ln,
    const float* __restrict__ gle, const float* __restrict__ ble,
    float* __restrict__ out_edge) {
    extern __shared__ char sm[];
    uint32_t* A  = (uint32_t*)(sm + A_OFF);
    uint32_t* B1 = (uint32_t*)(sm + B1_OFF);
    float* ps = (float*)(sm + PS_OFF);
    float* pq = (float*)(sm + PQ_OFF);
    const int t = threadIdx.x;
    const float* At = edge + (size_t)blockIdx.x * 16384;
    const uint32_t sb = smem_u32(sm);

    copy_tile_async(g_wsw, sb + B1_OFF, t);                 // W1
    copy_tile_async(g_wsw + TILE_U32, sb + B2_OFF, t);      // W2
    CP_COMMIT();
    load_atile(At, 128, A, t);
    CP_WAIT();
    __syncthreads();

    const int w = t >> 5, lane = t & 31, wm = w >> 2, wn = w & 3;
    const int gid = lane >> 2, lid = lane & 3;
    float acc[4][4][4];
    int cc[4];
#pragma unroll
    for (int nt = 0; nt < 4; nt++) cc[nt] = wn * 32 + nt * 8 + lid * 2;

    // ---- GEMM1: edge @ W1 ----
    mma_loop(sb + A_OFF, sb + B1_OFF, wm, wn, lane, acc);

    // ---- epilogue 1: +ns+nt, LN, relu -> B1 (fp16 tile) ----
    {
        const int s_tile = blockIdx.x >> 2, nbase = (blockIdx.x & 3) * 128;
#pragma unroll
        for (int nt = 0; nt < 4; nt++) {
            float2 ntv = *(const float2*)&g_pre[65536 + s_tile * 128 + cc[nt]];
#pragma unroll
            for (int mt = 0; mt < 4; mt++) {
                int r0 = wm * 64 + mt * 16 + gid;
                float2 n0 = *(const float2*)&g_pre[(nbase + r0) * 128 + cc[nt]];
                float2 n1 = *(const float2*)&g_pre[(nbase + r0 + 8) * 128 + cc[nt]];
                acc[mt][nt][0] += n0.x + ntv.x; acc[mt][nt][1] += n0.y + ntv.y;
                acc[mt][nt][2] += n1.x + ntv.x; acc[mt][nt][3] += n1.y + ntv.y;
            }
        }
        float mean[8], rstd[8];
        row_stats(acc, ps, pq, wm, wn, gid, lid, mean, rstd);
#pragma unroll
        for (int nt = 0; nt < 4; nt++) {
            float2 gv = *(const float2*)&g1m[cc[nt]];
            float2 bv2 = *(const float2*)&b1m[cc[nt]];
#pragma unroll
            for (int mt = 0; mt < 4; mt++) {
                int r0 = wm * 64 + mt * 16 + gid;
                float o0x = fmaxf((acc[mt][nt][0]-mean[mt*2])*rstd[mt*2]*gv.x + bv2.x, 0.f);
                float o0y = fmaxf((acc[mt][nt][1]-mean[mt*2])*rstd[mt*2]*gv.y + bv2.y, 0.f);
                float o1x = fmaxf((acc[mt][nt][2]-mean[mt*2+1])*rstd[mt*2+1]*gv.x + bv2.x, 0.f);
                float o1y = fmaxf((acc[mt][nt][3]-mean[mt*2+1])*rstd[mt*2+1]*gv.y + bv2.y, 0.f);
                B1[r0 * 68 + (cc[nt] >> 1)] = pack_h2(o0x, o0y);
                B1[(r0 + 8) * 68 + (cc[nt] >> 1)] = pack_h2(o1x, o1y);
            }
        }
    }
    __syncthreads();   // B1 = memory tile (fp16)

    // ---- coalesced bulk store of memory tile to gmem (tile format) ----
    {
        uint4* dst = (uint4*)(g_memt + (size_t)blockIdx.x * TILE_U32);
        const uint4* srcB = (const uint4*)B1;
#pragma unroll
        for (int j = 0; j < 9; j++) {
            int idx = t + j * 256;
            if (idx < 2176) dst[idx] = srcB[idx];
        }
    }

    // ---- GEMM2: memory @ W2 ----
    mma_loop(sb + B1_OFF, sb + B2_OFF, wm, wn, lane, acc);

    // ---- epilogue 2 ----
    {
#pragma unroll
        for (int nt = 0; nt < 4; nt++) {
            float2 bp = *(const float2*)&bpe[cc[nt]];
#pragma unroll
            for (int mt = 0; mt < 4; mt++) {
                acc[mt][nt][0] += bp.x; acc[mt][nt][1] += bp.y;
                acc[mt][nt][2] += bp.x; acc[mt][nt][3] += bp.y;
            }
        }
        float mean[8], rstd[8];
        row_stats(acc, ps, pq, wm, wn, gid, lid, mean, rstd);
#pragma unroll
        for (int nt = 0; nt < 4; nt++) {
            float2 g1 = *(const float2*)&gpe[cc[nt]];
            float2 b1 = *(const float2*)&bpe_ln[cc[nt]];
#pragma unroll
            for (int mt = 0; mt < 4; mt++) {
                int r0 = wm * 64 + mt * 16 + gid;
                float2 e0 = __half22float2(*(__half2*)&A[r0 * 68 + (cc[nt] >> 1)]);
                float2 e1 = __half22float2(*(__half2*)&A[(r0 + 8) * 68 + (cc[nt] >> 1)]);
                acc[mt][nt][0] = e0.x + fmaxf((acc[mt][nt][0]-mean[mt*2])*rstd[mt*2]*g1.x + b1.x, 0.f);
                acc[mt][nt][1] = e0.y + fmaxf((acc[mt][nt][1]-mean[mt*2])*rstd[mt*2]*g1.y + b1.y, 0.f);
                acc[mt][nt][2] = e1.x + fmaxf((acc[mt][nt][2]-mean[mt*2+1])*rstd[mt*2+1]*g1.x + b1.x, 0.f);
                acc[mt][nt][3] = e1.y + fmaxf((acc[mt][nt][3]-mean[mt*2+1])*rstd[mt*2+1]*g1.y + b1.y, 0.f);
            }
        }
        row_stats(acc, ps, pq, wm, wn, gid, lid, mean, rstd);
        float* orow = out_edge + (size_t)blockIdx.x * 16384;
#pragma unroll
        for (int nt = 0; nt < 4; nt++) {
            float2 g2 = *(const float2*)&gle[cc[nt]];
            float2 b2 = *(const float2*)&ble[cc[nt]];
#pragma unroll
            for (int mt = 0; mt < 4; mt++) {
                int r0 = wm * 64 + mt * 16 + gid;
                float2 o0, o1;
                o0.x = (acc[mt][nt][0]-mean[mt*2])*rstd[mt*2]*g2.x + b2.x;
                o0.y = (acc[mt][nt][1]-mean[mt*2])*rstd[mt*2]*g2.y + b2.y;
                o1.x = (acc[mt][nt][2]-mean[mt*2+1])*rstd[mt*2+1]*g2.x + b2.x;
                o1.y = (acc[mt][nt][3]-mean[mt*2+1])*rstd[mt*2+1]*g2.y + b2.y;
                *(float2*)&orow[r0 * 128 + cc[nt]] = o0;
                *(float2*)&orow[(r0 + 8) * 128 + cc[nt]] = o1;
            }
        }
    }
}

// ============ fused attention + out1 (512 threads, MMA both phases) ============
#define MH_OFF   0
#define QB_OFF   139264
#define ATT_OFF  141440
#define MK_OFF   157824
#define ATT2_OFF 158336
#define RPA_OFF  166528
#define RPB_OFF  170624
#define CS_OFF   174720
#define RS_OFF   175232
#define ATT_SMEM 175360
__global__ __launch_bounds__(512) void k_attn2(
    const unsigned char* __restrict__ mask,
    const float* __restrict__ wv, const float* __restrict__ bv,
    const float* __restrict__ node, const float* __restrict__ wo,
    const float* __restrict__ bo, const float* __restrict__ g2,
    const float* __restrict__ b2) {
    extern __shared__ char sm[];
    __half* mh = (__half*)(sm + MH_OFF);
    __half* qb = (__half*)(sm + QB_OFF);
    float* att = (float*)(sm + ATT_OFF);
    unsigned char* mk = (unsigned char*)(sm + MK_OFF);
    __half* att2 = (__half*)(sm + ATT2_OFF);
    const int n = blockIdx.x, t = threadIdx.x, w = t >> 5, lane = t & 31;
    const uint32_t sb = smem_u32(sm);

    for (int i = t; i < 1024; i += 512) {
        int h = i >> 7, c = i & 127;
        qb[h * 136 + c] = __float2half_rn(g_qh[n * 1024 + i]);
    }
    mk[t & 511] = mask[n * 512 + (t & 511)];
    {
        const int nhi = n >> 7, row = n & 127;
        const uint32_t* base = g_memt + (size_t)row * 68 + (size_t)nhi * TILE_U32;
#pragma unroll 4
        for (int j = 0; j < 16; j++) {
            int idx = t + j * 512;
            int s = idx >> 4, k4 = idx & 15;
            uint4 v = *(const uint4*)(base + (size_t)s * (4 * TILE_U32) + k4 * 4);
            *(uint4*)&mh[s * 136 + k4 * 8] = v;
        }
    }
    __syncthreads();

    // ---- scores via MMA: warp w covers s in [w*32, w*32+32) ----
    {
        const int l2 = lane & 15;
        const uint32_t aoffA = (uint32_t)((lane & 15) * 272 + (lane >> 4) * 16);
        const uint32_t qaddr = sb + QB_OFF + (uint32_t)((l2 & 7) * 272 + ((l2 >> 3) & 1) * 16);
        float acc[2][4];
#pragma unroll
        for (int mt = 0; mt < 2; mt++)
#pragma unroll
            for (int q = 0; q < 4; q++) acc[mt][q] = 0.f;
#pragma unroll
        for (int ks = 0; ks < 8; ks++) {
            uint32_t bq[2];
            LDSM2(bq[0], bq[1], qaddr + ks * 32);
#pragma unroll
            for (int mt = 0; mt < 2; mt++) {
                uint32_t a[4];
                LDSM4(a[0], a[1], a[2], a[3],
                      sb + MH_OFF + (w * 32 + mt * 16) * 272 + aoffA + ks * 32);
                mma_f16(acc[mt], a, bq);
            }
        }
        const int gid = lane >> 2, lid = lane & 3;
#pragma unroll
        for (int mt = 0; mt < 2; mt++) {
            int s = w * 32 + mt * 16 + gid;
            att[(2 * lid) * 512 + s]     = acc[mt][0];
            att[(2 * lid + 1) * 512 + s] = acc[mt][1];
            att[(2 * lid) * 512 + s + 8]     = acc[mt][2];
            att[(2 * lid + 1) * 512 + s + 8] = acc[mt][3];
        }
    }
    __syncthreads();

    // ---- softmax per head, apply mask ----
    if (w < 8) {
        const int h = w;
        float sc[16];
        float mx = -3.402823466e38f;
#pragma unroll
        for (int i = 0; i < 16; i++) {
            int s = lane + i * 32;
            sc[i] = mk[s] ? -3.402823466e38f : att[h * 512 + s];
            mx = fmaxf(mx, sc[i]);
        }
        mx = warp_max(mx);
        float sum = 0.f;
#pragma unroll
        for (int i = 0; i < 16; i++) { sc[i] = __expf(sc[i] - mx); sum += sc[i]; }
        sum = warp_sum(sum);
        float inv = 1.f / sum;
#pragma unroll
        for (int i = 0; i < 16; i++) att[h * 512 + lane + i * 32] = sc[i] * inv;
    }
    __syncthreads();

    // ---- convert att [h][s] fp32 -> att2 [s][8h] fp16 ----
    {
        int s = t;
        uint32_t p0 = pack_h2(att[0 * 512 + s], att[1 * 512 + s]);
        uint32_t p1 = pack_h2(att[2 * 512 + s], att[3 * 512 + s]);
        uint32_t p2 = pack_h2(att[4 * 512 + s], att[5 * 512 + s]);
        uint32_t p3 = pack_h2(att[6 * 512 + s], att[7 * 512 + s]);
        *(uint4*)&att2[s * 8] = make_uint4(p0, p1, p2, p3);
    }
    __syncthreads();

    // ---- weighted sum via MMA: r(c x h) = mem^T @ att ----
    {
        const int ctile = w >> 1, khalf = w & 1;
        const uint32_t a_base = sb + MH_OFF
            + (uint32_t)((khalf * 256 + (lane & 7) + ((lane >> 4) & 1) * 8) * 272
                         + ctile * 32 + ((lane >> 3) & 1) * 16);
        const uint32_t b_base = sb + ATT2_OFF
            + (uint32_t)((khalf * 256 + (lane & 15)) * 16);
        float accw[4] = {0.f, 0.f, 0.f, 0.f};
#pragma unroll
        for (int kk = 0; kk < 16; kk++) {
            uint32_t a[4], b[2];
            LDSM4T(a[0], a[1], a[2], a[3], a_base + kk * 16 * 272);
            LDSM2T(b[0], b[1], b_base + kk * 256);
            mma_f16(accw, a, b);
        }
        float* rp = (float*)(sm + (khalf ? RPB_OFF : RPA_OFF));
        const int gid = lane >> 2, lid = lane & 3;
        int c0 = ctile * 16 + gid, h0 = 2 * lid;
        rp[c0 * 8 + h0] = accw[0];       rp[c0 * 8 + h0 + 1] = accw[1];
        rp[(c0 + 8) * 8 + h0] = accw[2]; rp[(c0 + 8) * 8 + h0 + 1] = accw[3];
    }
    __syncthreads();

    // ---- ctx = r @ wv + bv ----
    float* rpA = (float*)(sm + RPA_OFF);
    float* rpB = (float*)(sm + RPB_OFF);
    float* cs = (float*)(sm + CS_OFF);
    if (t < 128) {
        int h = t >> 4;
        float a = bv[t];
#pragma unroll 8
        for (int c = 0; c < 128; c++)
            a += (rpA[c * 8 + h] + rpB[c * 8 + h]) * wv[c * 128 + t];
        cs[t] = a;
    }
    __syncthreads();

    // ---- x1 = LN(node + ctx @ wo + bo) ----
    float* rsum = (float*)(sm + RS_OFF);
    float* rsq  = (float*)(sm + RS_OFF + 64);
    float aval = 0.f;
    if (t < 128) {
        aval = bo[t] + node[n * 128 + t];
#pragma unroll 8
        for (int c = 0; c < 128; c++) aval += cs[c] * wo[c * 128 + t];
        float s1 = warp_sum(aval), s2 = warp_sum(aval * aval);
        if ((t & 31) == 0) { rsum[t >> 5] = s1; rsq[t >> 5] = s2; }
    }
    __syncthreads();
    if (t < 128) {
        float sum = rsum[0] + rsum[1] + rsum[2] + rsum[3];
        float sq  = rsq[0] + rsq[1] + rsq[2] + rsq[3];
        float mean = sum * (1.f / 128.f);
        float rs = rsqrtf(sq * (1.f / 128.f) - mean * mean + LN_EPS);
        g_x1[n * 128 + t] = (aval - mean) * rs * g2[t] + b2[t];
    }
}

// ============ final: out_x = LN(x1 + sum_k ffp[k] + b2) ============
__global__ void k_fin(const float* __restrict__ b2, const float* __restrict__ g3,
                      const float* __restrict__ b3, float* __restrict__ out_x) {
    int row = blockIdx.x, d = threadIdx.x;
    __shared__ float rsum[4], rsq[4];
    float v = g_x1[row * 128 + d] + b2[d];
#pragma unroll
    for (int k = 0; k < 16; k++) v += g_ffp[k * 65536 + row * 128 + d];
    float s1 = warp_sum(v), s2 = warp_sum(v * v);
    if ((d & 31) == 0) { rsum[d >> 5] = s1; rsq[d >> 5] = s2; }
    __syncthreads();
    float sum = rsum[0] + rsum[1] + rsum[2] + rsum[3];
    float sq = rsq[0] + rsq[1] + rsq[2] + rsq[3];
    float mean = sum * (1.f / 128.f);
    float rs = rsqrtf(sq * (1.f / 128.f) - mean * mean + LN_EPS);
    out_x[row * 128 + d] = (v - mean) * rs * g3[d] + b3[d];
}

extern "C" void kernel_launch(void* const* d_in, const int* in_sizes, int n_in,
                              void* d_out, int out_size) {
    (void)in_sizes; (void)n_in; (void)out_size;
    const float* node     = (const float*)d_in[0];
    const float* edge     = (const float*)d_in[1];
    const unsigned char* mask = (const unsigned char*)d_in[2];
    const float* w_mem_e  = (const float*)d_in[3];
    const float* w_mem_s  = (const float*)d_in[4];
    const float* w_mem_t  = (const float*)d_in[5];
    const float* b_mem    = (const float*)d_in[6];
    const float* g_ln_mem = (const float*)d_in[7];
    const float* b_ln_mem = (const float*)d_in[8];
    const float* w_pe     = (const float*)d_in[9];
    const float* b_pe     = (const float*)d_in[10];
    const float* g_ln_pe  = (const float*)d_in[11];
    const float* b_ln_pe  = (const float*)d_in[12];
    const float* g_ln_edge= (const float*)d_in[13];
    const float* b_ln_edge= (const float*)d_in[14];
    const float* wq       = (const float*)d_in[15];
    const float* bq       = (const float*)d_in[16];
    const float* wk       = (const float*)d_in[17];
    /* bk (d_in[18]) provably drops out of softmax */
    const float* wv       = (const float*)d_in[19];
    const float* bv       = (const float*)d_in[20];
    const float* wo       = (const float*)d_in[21];
    const float* bo       = (const float*)d_in[22];
    const float* g_ln2    = (const float*)d_in[23];
    const float* b_ln2    = (const float*)d_in[24];
    const float* w_ff1    = (const float*)d_in[25];
    const float* b_ff1    = (const float*)d_in[26];
    const float* w_ff2    = (const float*)d_in[27];
    const float* b_ff2    = (const float*)d_in[28];
    const float* g_ln3    = (const float*)d_in[29];
    const float* b_ln3    = (const float*)d_in[30];

    float* out_x = (float*)d_out;
    float* out_edge = (float*)d_out + NSEQ * DMODEL;

    cudaFuncSetAttribute(k_fused, cudaFuncAttributeMaxDynamicSharedMemorySize, GSMEM);
    cudaFuncSetAttribute(k_tileA, cudaFuncAttributeMaxDynamicSharedMemorySize, TSMEM);
    cudaFuncSetAttribute(k_tile, cudaFuncAttributeMaxDynamicSharedMemorySize, TSMEM);
    cudaFuncSetAttribute(k_attn2, cudaFuncAttributeMaxDynamicSharedMemorySize, ATT_SMEM);
    cudaFuncSetAttribute(k_qh, cudaFuncAttributeMaxDynamicSharedMemorySize, QH_SMEM);

    float* d_pre;  cudaGetSymbolAddress((void**)&d_pre, g_pre);
    float* d_bcat; cudaGetSymbolAddress((void**)&d_bcat, g_bcat);
    float* d_h;    cudaGetSymbolAddress((void**)&d_h, g_h);
    float* d_ffp;  cudaGetSymbolAddress((void**)&d_ffp, g_ffp);
    float* d_x1;   cudaGetSymbolAddress((void**)&d_x1, g_x1);

    k_wpack<<<5, 256>>>(w_mem_e, w_pe, w_mem_s, w_mem_t, wq, b_mem, bq);
    // [ns|nt|q] = node @ [w_mem_s|w_mem_t|wq] + [b_mem|0|bq]
    k_tileA<<<dim3(4, 3), 256, TSMEM>>>(node, d_pre, d_bcat);
    k_qh<<<128, 256, QH_SMEM>>>(wk);
    // memory (fp16 tile format) + edge_new in one pass
    k_fused<<<2048, 256, GSMEM>>>(edge, g_ln_mem, b_ln_mem,
                                  b_pe, g_ln_pe, b_ln_pe, g_ln_edge, b_ln_edge, out_edge);
    k_attn2<<<512, 512, ATT_SMEM>>>(mask, wv, bv, node, wo, bo, g_ln2, b_ln2);
    // h = relu(x1 @ w1 + b1)
    k_tile<<<dim3(4, 16), 256, TSMEM>>>(d_x1, 128, 16384, 0, w_ff1, 2048, 128,
                                        d_h, 2048, 262144, 128, b_ff1, 128, 1);
    // ffp[k] = h_chunk @ w2_chunk
    k_tile<<<dim3(4, 16), 256, TSMEM>>>(d_h, 2048, 262144, 128, w_ff2, 128, 16384,
                                        d_ffp, 128, 16384, 65536, nullptr, 0, 0);
    k_fin<<<512, 128>>>(b_ff2, g_ln3, b_ln3, out_x);
}